// round 15
// baseline (speedup 1.0000x reference)
#include <cuda_runtime.h>
#include <cuda_bf16.h>

// SoftPool2d: 3x3 window, stride 2, pad 1; zero-padding participates in softmax.
// x: [16,96,224,224] f32 -> out: [16,96,112,112] f32.
//
// Converged champion body (R4/R11/R12/R14): each thread computes a 2x2 output
// tile from a 5x5 input patch: 10x plain LDG.128 (16B-aligned), 25 EX2, 2 STG.64.
// alpha folded in per-thread via alpha*log2e = log2(1 + 2^(raw*log2e)) -> one launch.
// This round: block 256 -> 512 (grid 9408, exact). Same occupancy ceiling and
// 32 regs; isolates CTA-granularity scheduling/locality. Everything else is
// byte-identical to the champion.
//
// Measured sweep (R3-R14): tile 2x2 beats 1x1/2x4; aligned-float4 halo beats
// scalar/shuffle; NC/stcs hints regress; persistent grid regresses (loses
// cross-iteration MLP). Champion: 55.1us kernel @ 6.7TB/s = ~96% of the B300
// LTS chip cap, traffic at the ~370MB compulsory floor.

#define H_IN    224
#define W_IN    224
#define H_OUT   112
#define W_OUT   112
#define PLANE_IN  (H_IN * W_IN)     // 50176
#define PLANE_OUT (H_OUT * W_OUT)   // 12544
#define PQ        56                 // output pairs per dim
#define TILES_PER_PLANE (PQ * PQ)    // 3136
#define N_PLANES  (16 * 96)          // 1536
#define TOTAL_TILES (TILES_PER_PLANE * N_PLANES)  // 4,816,896 = 9408 * 512 exactly

#define BLOCK 512

__device__ __forceinline__ float ex2f(float x) {
    float r;
    asm("ex2.approx.ftz.f32 %0, %1;" : "=f"(r) : "f"(x));
    return r;
}

__device__ __forceinline__ float lg2f(float x) {
    float r;
    asm("lg2.approx.ftz.f32 %0, %1;" : "=f"(r) : "f"(x));
    return r;
}

__device__ __forceinline__ float frcp(float x) {
    float r;
    asm("rcp.approx.ftz.f32 %0, %1;" : "=f"(r) : "f"(x));
    return r;
}

__global__ __launch_bounds__(BLOCK)
void softpool_kernel(const float* __restrict__ x,
                     const float* __restrict__ raw_alpha,
                     float* __restrict__ out) {
    unsigned idx = blockIdx.x * (unsigned)BLOCK + threadIdx.x;  // grid sized exactly

    // c = alpha * log2(e) = log2(1 + exp(raw_alpha))
    const float c = lg2f(1.0f + ex2f(__ldg(raw_alpha) * 1.44269504088896340736f));

    unsigned p  = idx % PQ;          // output col pair: cols 2p, 2p+1
    unsigned t  = idx / PQ;
    unsigned q  = t % PQ;            // output row pair: rows 2q, 2q+1
    unsigned nc = t / PQ;

    const float* plane = x + (size_t)nc * PLANE_IN;

    // Input patch: rows 4q-1..4q+3, cols 4p-1..4p+3.
    // Max index = 4*55+3 = 223 -> only top/left ever pad.
    int row0 = 4 * (int)q - 1;
    int colB = 4 * (int)p;                 // 16B-aligned float4 base (cols 4p..4p+3)
    int colA = colB >= 4 ? colB - 4 : 0;   // cols 4p-4..4p-1 (clamped for p=0, stays aligned)
    bool left = (p == 0);
    bool top  = (q == 0);

    float num00 = 0.f, num01 = 0.f, num10 = 0.f, num11 = 0.f;
    float den00 = 0.f, den01 = 0.f, den10 = 0.f, den11 = 0.f;

#pragma unroll
    for (int r = 0; r < 5; ++r) {
        int rr = row0 + r;
        int rc = rr < 0 ? 0 : rr;          // clamp addr; values zeroed below
        const float* rp = plane + (size_t)rc * W_IN;

        float4 A = *(const float4*)(rp + colA);  // cols 4p-4..4p-1 (need .w)
        float4 B = *(const float4*)(rp + colB);  // cols 4p..4p+3

        float v0 = left ? 0.f : A.w;
        float v1 = B.x, v2 = B.y, v3 = B.z, v4 = B.w;
        if (top && r == 0) { v0 = 0.f; v1 = 0.f; v2 = 0.f; v3 = 0.f; v4 = 0.f; }

        float e0 = ex2f(c * v0), e1 = ex2f(c * v1), e2 = ex2f(c * v2);
        float e3 = ex2f(c * v3), e4 = ex2f(c * v4);

        // left window = cols {0,1,2}, right window = cols {2,3,4}; col 2 shared
        float ve2 = v2 * e2;
        float dl = e0 + e1 + e2;
        float dr = e2 + e3 + e4;
        float nl = fmaf(v0, e0, fmaf(v1, e1, ve2));
        float nr = fmaf(v3, e3, fmaf(v4, e4, ve2));

        // rows 0..2 -> out row 2q; rows 2..4 -> out row 2q+1 (row 2 shared)
        if (r <= 2) { den00 += dl; den01 += dr; num00 += nl; num01 += nr; }
        if (r >= 2) { den10 += dl; den11 += dr; num10 += nl; num11 += nr; }
    }

    float* op = out + (size_t)nc * PLANE_OUT + (size_t)(2u * q) * W_OUT + 2u * p;
    *(float2*)op           = make_float2(num00 * frcp(den00), num01 * frcp(den01));
    *(float2*)(op + W_OUT) = make_float2(num10 * frcp(den10), num11 * frcp(den11));
}

extern "C" void kernel_launch(void* const* d_in, const int* in_sizes, int n_in,
                              void* d_out, int out_size) {
    const float* x         = (const float*)d_in[0];
    const float* raw_alpha = (const float*)d_in[1];
    float*       out       = (float*)d_out;

    const int grid = TOTAL_TILES / BLOCK;  // 9408, exact
    softpool_kernel<<<grid, BLOCK>>>(x, raw_alpha, out);
}

// round 16
// speedup vs baseline: 1.0108x; 1.0108x over previous
#include <cuda_runtime.h>
#include <cuda_bf16.h>

// SoftPool2d: 3x3 window, stride 2, pad 1; zero-padding participates in softmax.
// x: [16,96,224,224] f32 -> out: [16,96,112,112] f32.
//
// FINAL kernel (converged champion, reproduced in R4/R11/R12/R14 at 55.1-55.3us
// kernel / 59.4-59.6us total). Each thread computes a 2x2 output tile from a
// 5x5 input patch: 10x plain LDG.128 (16B-aligned), 25 EX2 (ex2.approx),
// 2 STG.64. alpha folded in per-thread via the MUFU identity
//   alpha*log2e = log2(1 + 2^(raw_alpha*log2e))  -> single launch, no prep.
//
// Complete measured sweep (R3-R15):
//  - tile: 1x1 83.7us / 2x2 55.1us WINNER / 2x4 56.1us
//  - halo: aligned float4 WINNER / scalar LDG (occ loss) / shfl_up (occ loss)
//  - cache hints: NC loads + streaming stores regress (56.1us)
//  - launch: exact-grid waves WINNER / persistent grid 57.3us (loses MLP)
//  - block: 256 WINNER / 512 57.2us (coarser CLC balancing)
// Runs at 6.71TB/s = ~96% of the B300 LTS chip cap (~6300 B/cyc), traffic at
// the ~370MB compulsory floor. This is the roofline for this op on sm_103a.

#define H_IN    224
#define W_IN    224
#define H_OUT   112
#define W_OUT   112
#define PLANE_IN  (H_IN * W_IN)     // 50176
#define PLANE_OUT (H_OUT * W_OUT)   // 12544
#define PQ        56                 // output pairs per dim
#define TILES_PER_PLANE (PQ * PQ)    // 3136
#define N_PLANES  (16 * 96)          // 1536
#define TOTAL_TILES (TILES_PER_PLANE * N_PLANES)  // 4,816,896 = 18816 * 256 exactly

__device__ __forceinline__ float ex2f(float x) {
    float r;
    asm("ex2.approx.ftz.f32 %0, %1;" : "=f"(r) : "f"(x));
    return r;
}

__device__ __forceinline__ float lg2f(float x) {
    float r;
    asm("lg2.approx.ftz.f32 %0, %1;" : "=f"(r) : "f"(x));
    return r;
}

__device__ __forceinline__ float frcp(float x) {
    float r;
    asm("rcp.approx.ftz.f32 %0, %1;" : "=f"(r) : "f"(x));
    return r;
}

__global__ __launch_bounds__(256)
void softpool_kernel(const float* __restrict__ x,
                     const float* __restrict__ raw_alpha,
                     float* __restrict__ out) {
    unsigned idx = blockIdx.x * 256u + threadIdx.x;   // grid sized exactly

    // c = alpha * log2(e) = log2(1 + exp(raw_alpha))
    const float c = lg2f(1.0f + ex2f(__ldg(raw_alpha) * 1.44269504088896340736f));

    unsigned p  = idx % PQ;          // output col pair: cols 2p, 2p+1
    unsigned t  = idx / PQ;
    unsigned q  = t % PQ;            // output row pair: rows 2q, 2q+1
    unsigned nc = t / PQ;

    const float* plane = x + (size_t)nc * PLANE_IN;

    // Input patch: rows 4q-1..4q+3, cols 4p-1..4p+3.
    // Max index = 4*55+3 = 223 -> only top/left ever pad.
    int row0 = 4 * (int)q - 1;
    int colB = 4 * (int)p;                 // 16B-aligned float4 base (cols 4p..4p+3)
    int colA = colB >= 4 ? colB - 4 : 0;   // cols 4p-4..4p-1 (clamped for p=0, stays aligned)
    bool left = (p == 0);
    bool top  = (q == 0);

    float num00 = 0.f, num01 = 0.f, num10 = 0.f, num11 = 0.f;
    float den00 = 0.f, den01 = 0.f, den10 = 0.f, den11 = 0.f;

#pragma unroll
    for (int r = 0; r < 5; ++r) {
        int rr = row0 + r;
        int rc = rr < 0 ? 0 : rr;          // clamp addr; values zeroed below
        const float* rp = plane + (size_t)rc * W_IN;

        float4 A = *(const float4*)(rp + colA);  // cols 4p-4..4p-1 (need .w)
        float4 B = *(const float4*)(rp + colB);  // cols 4p..4p+3

        float v0 = left ? 0.f : A.w;
        float v1 = B.x, v2 = B.y, v3 = B.z, v4 = B.w;
        if (top && r == 0) { v0 = 0.f; v1 = 0.f; v2 = 0.f; v3 = 0.f; v4 = 0.f; }

        float e0 = ex2f(c * v0), e1 = ex2f(c * v1), e2 = ex2f(c * v2);
        float e3 = ex2f(c * v3), e4 = ex2f(c * v4);

        // left window = cols {0,1,2}, right window = cols {2,3,4}; col 2 shared
        float ve2 = v2 * e2;
        float dl = e0 + e1 + e2;
        float dr = e2 + e3 + e4;
        float nl = fmaf(v0, e0, fmaf(v1, e1, ve2));
        float nr = fmaf(v3, e3, fmaf(v4, e4, ve2));

        // rows 0..2 -> out row 2q; rows 2..4 -> out row 2q+1 (row 2 shared)
        if (r <= 2) { den00 += dl; den01 += dr; num00 += nl; num01 += nr; }
        if (r >= 2) { den10 += dl; den11 += dr; num10 += nl; num11 += nr; }
    }

    float* op = out + (size_t)nc * PLANE_OUT + (size_t)(2u * q) * W_OUT + 2u * p;
    *(float2*)op           = make_float2(num00 * frcp(den00), num01 * frcp(den01));
    *(float2*)(op + W_OUT) = make_float2(num10 * frcp(den10), num11 * frcp(den11));
}

extern "C" void kernel_launch(void* const* d_in, const int* in_sizes, int n_in,
                              void* d_out, int out_size) {
    const float* x         = (const float*)d_in[0];
    const float* raw_alpha = (const float*)d_in[1];
    float*       out       = (float*)d_out;

    const int block = 256;
    const int grid  = TOTAL_TILES / block;  // 18816, exact
    softpool_kernel<<<grid, block>>>(x, raw_alpha, out);
}

// round 17
// speedup vs baseline: 1.0118x; 1.0011x over previous
#include <cuda_runtime.h>
#include <cuda_bf16.h>

// SoftPool2d: 3x3 window, stride 2, pad 1; zero-padding participates in softmax.
// x: [16,96,224,224] f32 -> out: [16,96,112,112] f32.
//
// Converged champion body (R4/R11/R12/R14/R16): each thread computes a 2x2
// output tile from a 5x5 input patch: 10x plain LDG.128 (16B-aligned), 25 EX2,
// 2 STG.64. alpha folded per-thread via alpha*log2e = log2(1 + 2^(raw*log2e)).
// This round completes the block-size axis: 128 threads/block (grid 37632,
// exact; 16 CTAs/SM at the same 2048-thread ceiling). 512 regressed (57.2us,
// coarse CLC quanta), 256 is champion (55.1us); testing whether finer quanta
// shave the wave-boundary imbalance/tail further.
//
// Measured sweep (R3-R16): tile 2x2 beats 1x1/2x4; aligned-float4 halo beats
// scalar/shuffle; NC/stcs regress; persistent grid regresses (loses MLP).
// Champion runs at 6.7TB/s = ~96% of the B300 LTS chip cap, traffic at the
// fully-deduped ~370MB floor.

#define H_IN    224
#define W_IN    224
#define H_OUT   112
#define W_OUT   112
#define PLANE_IN  (H_IN * W_IN)     // 50176
#define PLANE_OUT (H_OUT * W_OUT)   // 12544
#define PQ        56                 // output pairs per dim
#define TILES_PER_PLANE (PQ * PQ)    // 3136
#define N_PLANES  (16 * 96)          // 1536
#define TOTAL_TILES (TILES_PER_PLANE * N_PLANES)  // 4,816,896 = 37632 * 128 exactly

#define BLOCK 128

__device__ __forceinline__ float ex2f(float x) {
    float r;
    asm("ex2.approx.ftz.f32 %0, %1;" : "=f"(r) : "f"(x));
    return r;
}

__device__ __forceinline__ float lg2f(float x) {
    float r;
    asm("lg2.approx.ftz.f32 %0, %1;" : "=f"(r) : "f"(x));
    return r;
}

__device__ __forceinline__ float frcp(float x) {
    float r;
    asm("rcp.approx.ftz.f32 %0, %1;" : "=f"(r) : "f"(x));
    return r;
}

__global__ __launch_bounds__(BLOCK)
void softpool_kernel(const float* __restrict__ x,
                     const float* __restrict__ raw_alpha,
                     float* __restrict__ out) {
    unsigned idx = blockIdx.x * (unsigned)BLOCK + threadIdx.x;  // grid sized exactly

    // c = alpha * log2(e) = log2(1 + exp(raw_alpha))
    const float c = lg2f(1.0f + ex2f(__ldg(raw_alpha) * 1.44269504088896340736f));

    unsigned p  = idx % PQ;          // output col pair: cols 2p, 2p+1
    unsigned t  = idx / PQ;
    unsigned q  = t % PQ;            // output row pair: rows 2q, 2q+1
    unsigned nc = t / PQ;

    const float* plane = x + (size_t)nc * PLANE_IN;

    // Input patch: rows 4q-1..4q+3, cols 4p-1..4p+3.
    // Max index = 4*55+3 = 223 -> only top/left ever pad.
    int row0 = 4 * (int)q - 1;
    int colB = 4 * (int)p;                 // 16B-aligned float4 base (cols 4p..4p+3)
    int colA = colB >= 4 ? colB - 4 : 0;   // cols 4p-4..4p-1 (clamped for p=0, stays aligned)
    bool left = (p == 0);
    bool top  = (q == 0);

    float num00 = 0.f, num01 = 0.f, num10 = 0.f, num11 = 0.f;
    float den00 = 0.f, den01 = 0.f, den10 = 0.f, den11 = 0.f;

#pragma unroll
    for (int r = 0; r < 5; ++r) {
        int rr = row0 + r;
        int rc = rr < 0 ? 0 : rr;          // clamp addr; values zeroed below
        const float* rp = plane + (size_t)rc * W_IN;

        float4 A = *(const float4*)(rp + colA);  // cols 4p-4..4p-1 (need .w)
        float4 B = *(const float4*)(rp + colB);  // cols 4p..4p+3

        float v0 = left ? 0.f : A.w;
        float v1 = B.x, v2 = B.y, v3 = B.z, v4 = B.w;
        if (top && r == 0) { v0 = 0.f; v1 = 0.f; v2 = 0.f; v3 = 0.f; v4 = 0.f; }

        float e0 = ex2f(c * v0), e1 = ex2f(c * v1), e2 = ex2f(c * v2);
        float e3 = ex2f(c * v3), e4 = ex2f(c * v4);

        // left window = cols {0,1,2}, right window = cols {2,3,4}; col 2 shared
        float ve2 = v2 * e2;
        float dl = e0 + e1 + e2;
        float dr = e2 + e3 + e4;
        float nl = fmaf(v0, e0, fmaf(v1, e1, ve2));
        float nr = fmaf(v3, e3, fmaf(v4, e4, ve2));

        // rows 0..2 -> out row 2q; rows 2..4 -> out row 2q+1 (row 2 shared)
        if (r <= 2) { den00 += dl; den01 += dr; num00 += nl; num01 += nr; }
        if (r >= 2) { den10 += dl; den11 += dr; num10 += nl; num11 += nr; }
    }

    float* op = out + (size_t)nc * PLANE_OUT + (size_t)(2u * q) * W_OUT + 2u * p;
    *(float2*)op           = make_float2(num00 * frcp(den00), num01 * frcp(den01));
    *(float2*)(op + W_OUT) = make_float2(num10 * frcp(den10), num11 * frcp(den11));
}

extern "C" void kernel_launch(void* const* d_in, const int* in_sizes, int n_in,
                              void* d_out, int out_size) {
    const float* x         = (const float*)d_in[0];
    const float* raw_alpha = (const float*)d_in[1];
    float*       out       = (float*)d_out;

    const int grid = TOTAL_TILES / BLOCK;  // 37632, exact
    softpool_kernel<<<grid, BLOCK>>>(x, raw_alpha, out);
}